// round 1
// baseline (speedup 1.0000x reference)
#include <cuda_runtime.h>
#include <math.h>

#define BB   128
#define SS   512
#define CC   256
#define DGH  256
#define DOO  4
#define GG   10
#define NCTA 128

#define OUT_PI   (BB*SS*DOO)                    /* 262144  */
#define OUT_SG   (OUT_PI + BB*SS*GG)            /* 917504  */
#define OUT_MU   (OUT_SG + BB*SS*GG*DOO)        /* 3538944 */
#define OUT_MASK (OUT_MU + BB*SS*GG*DOO)        /* 6160384 */

// ---------------- scratch (static device globals; no cudaMalloc) ------------
__device__ float g_pn[BB*SS*DOO];        // prenet output [b][s][d]
__device__ float g_gi0[SS*768*BB];       // precomputed x@Wih0^T + bih0, layout [s][col][b]
__device__ float g_h0[2][DGH*BB];        // h0 double buffer, layout [u][b]
__device__ float g_h1[DGH*BB];           // h1, layout [u][b]
__device__ float g_H[(size_t)SS*DGH*BB]; // h1 history, layout [s][u][b]
__device__ unsigned long long g_bar = 0ULL;

__device__ __forceinline__ float sigmoidf_(float x){ return 1.f/(1.f + expf(-x)); }

__device__ __forceinline__ void grid_barrier(){
    __syncthreads();
    if (threadIdx.x == 0){
        unsigned long long old = atomicAdd(&g_bar, 1ULL);
        unsigned long long target = old - (old & (unsigned long long)(NCTA-1)) + (unsigned long long)NCTA;
        while (*(volatile unsigned long long*)&g_bar < target) { }
    }
    __syncthreads();
}

// ---------------- kernel 1: prenet = prev @ W_pre^T + b_pre -----------------
__global__ void prenet_kernel(const float* __restrict__ tgt,
                              const float* __restrict__ W_pre,
                              const float* __restrict__ b_pre){
    int idx = blockIdx.x*256 + threadIdx.x;
    if (idx >= BB*SS*DOO) return;
    int d = idx & 3;
    int s = (idx >> 2) & (SS-1);
    int b = idx >> 11;
    float v = b_pre[d];
    if (s > 0){
        const float* pv = tgt + ((size_t)(b*SS + s - 1))*DOO;
        #pragma unroll
        for (int e = 0; e < 4; e++) v += pv[e]*W_pre[d*DOO + e];
    }
    g_pn[idx] = v;
}

// ---------------- kernel 2: gi0 = xs @ Wih0^T + bih0 ------------------------
// output layout g_gi0[(s*768 + c)*128 + b]
__global__ __launch_bounds__(256) void gi0_gemm(const float* __restrict__ enc,
                                                const float* __restrict__ Wih0,
                                                const float* __restrict__ bih0){
    __shared__ float As[32][68];
    __shared__ float Ws[32][68];
    const int s  = blockIdx.z;
    const int c0 = blockIdx.y * 64;
    const int b0 = blockIdx.x * 64;
    const int t  = threadIdx.x;
    const int bg = t & 15, cg = t >> 4;
    float acc[4][4];
    #pragma unroll
    for (int i = 0; i < 4; i++)
        #pragma unroll
        for (int j = 0; j < 4; j++) acc[i][j] = 0.f;

    for (int kk = 0; kk < 260; kk += 32){
        for (int i = t; i < 2048; i += 256){
            int k = i >> 6, b = i & 63;
            int kg = kk + k;
            float v = 0.f;
            if (kg < 260){
                if (kg < 256) v = enc[(((size_t)(b0+b))*SS + s)*CC + kg];
                else          v = g_pn[(((size_t)(b0+b))*SS + s)*DOO + (kg-256)];
            }
            As[k][b] = v;
        }
        for (int i = t; i < 2048; i += 256){
            int k = i >> 6, c = i & 63;
            int kg = kk + k;
            Ws[k][c] = (kg < 260) ? Wih0[(size_t)(c0+c)*260 + kg] : 0.f;
        }
        __syncthreads();
        #pragma unroll
        for (int k = 0; k < 32; k++){
            float4 a = *(const float4*)&As[k][bg*4];
            float4 w = *(const float4*)&Ws[k][cg*4];
            acc[0][0] += w.x*a.x; acc[0][1] += w.x*a.y; acc[0][2] += w.x*a.z; acc[0][3] += w.x*a.w;
            acc[1][0] += w.y*a.x; acc[1][1] += w.y*a.y; acc[1][2] += w.y*a.z; acc[1][3] += w.y*a.w;
            acc[2][0] += w.z*a.x; acc[2][1] += w.z*a.y; acc[2][2] += w.z*a.z; acc[2][3] += w.z*a.w;
            acc[3][0] += w.w*a.x; acc[3][1] += w.w*a.y; acc[3][2] += w.w*a.z; acc[3][3] += w.w*a.w;
        }
        __syncthreads();
    }
    #pragma unroll
    for (int ci = 0; ci < 4; ci++){
        int c = c0 + cg*4 + ci;
        float bias = bih0[c];
        float4 o = make_float4(acc[ci][0]+bias, acc[ci][1]+bias, acc[ci][2]+bias, acc[ci][3]+bias);
        *(float4*)&g_gi0[((size_t)s*768 + c)*BB + b0 + bg*4] = o;
    }
}

// ---------------- kernel 3: persistent GRU recurrence -----------------------
// 128 CTAs = 64 unit-groups (4 units each) x 2 batch-halves (64 batches each)
__global__ void __launch_bounds__(256, 1) rec_kernel(
    const float* __restrict__ Whh0, const float* __restrict__ bhh0,
    const float* __restrict__ Wih1, const float* __restrict__ bih1,
    const float* __restrict__ Whh1, const float* __restrict__ bhh1)
{
    extern __shared__ float sm[];
    float* wA   = sm;                // 24*256 : gh0/gh1 weight rows
    float* wB   = wA + 24*256;       // 12*256 : gi1 weight rows
    float* hs0  = wB + 12*256;       // 64*64  : h staging
    float* hs1  = hs0 + 64*64;       // 64*64
    float* gh1s = hs1 + 64*64;       // 12*64  : gh1 carry across phases

    const int t = threadIdx.x;
    const int w = t >> 5, l = t & 31;
    const int ug = blockIdx.x >> 1, bh = blockIdx.x & 1;
    const int u0 = ug * 4, b0 = bh * 64;

    // load weight slices to smem (kept resident all 512 steps)
    for (int i = t; i < 24*256; i += 256){
        int row = i >> 8, k = i & 255;
        int tr = row/3, g = row - tr*3;
        const float* W = (tr < 4) ? Whh0 : Whh1;
        int u = u0 + (tr & 3);
        wA[i] = W[(size_t)(g*256 + u)*256 + k];
    }
    for (int i = t; i < 12*256; i += 256){
        int row = i >> 8, k = i & 255;
        int ui = row/3, g = row - ui*3;
        wB[i] = Wih1[(size_t)(g*256 + u0 + ui)*256 + k];
    }

    // per-thread biases
    float bA0=0.f, bA1=0.f, bA2=0.f;
    if (w < 4){ int u = u0 + w; bA0 = bhh0[u]; bA1 = bhh0[256+u]; bA2 = bhh0[512+u]; }
    const int uiB = w & 3, hhB = w >> 2;
    const int uB  = u0 + uiB;
    const int blB = hhB*32 + l;
    const float bI0 = bih1[uB], bI1 = bih1[256+uB], bI2 = bih1[512+uB];
    const float bH0 = bhh1[uB], bH1 = bhh1[256+uB], bH2 = bhh1[512+uB];

    // zero initial state (owned slice), must re-run on every launch
    { int ui2 = t >> 6, bz = t & 63;
      g_h0[0][(u0+ui2)*BB + b0 + bz] = 0.f;
      g_h1[(u0+ui2)*BB + b0 + bz]    = 0.f; }
    __threadfence();
    grid_barrier();

    for (int step = 0; step < SS; step++){
        const int cur = step & 1, nxt = cur ^ 1;

        // ---------------- Phase A: gh0 = h0@Whh0^T, gh1 = h1@Whh1^T --------
        float acc0=0.f,acc1=0.f,acc2=0.f,acc3=0.f,acc4=0.f,acc5=0.f;
        const float* hsrc = (w < 4) ? hs0 : hs1;
        const float* wr0 = wA + (w*3+0)*256;
        const float* wr1 = wA + (w*3+1)*256;
        const float* wr2 = wA + (w*3+2)*256;
        for (int kt = 0; kt < 4; kt++){
            for (int i = t; i < 1024; i += 256){
                int k = i >> 4, b4 = i & 15;
                ((float4*)hs0)[i] = __ldcg((const float4*)&g_h0[cur][(kt*64+k)*BB + b0 + b4*4]);
                ((float4*)hs1)[i] = __ldcg((const float4*)&g_h1[(kt*64+k)*BB + b0 + b4*4]);
            }
            __syncthreads();
            const float* wp0 = wr0 + kt*64;
            const float* wp1 = wr1 + kt*64;
            const float* wp2 = wr2 + kt*64;
            #pragma unroll
            for (int k = 0; k < 64; k += 4){
                float wq0[4], wq1[4], wq2[4];
                *(float4*)wq0 = *(const float4*)&wp0[k];
                *(float4*)wq1 = *(const float4*)&wp1[k];
                *(float4*)wq2 = *(const float4*)&wp2[k];
                #pragma unroll
                for (int q = 0; q < 4; q++){
                    float2 h = *(const float2*)&hsrc[(k+q)*64 + (l<<1)];
                    acc0 += h.x*wq0[q]; acc1 += h.x*wq1[q]; acc2 += h.x*wq2[q];
                    acc3 += h.y*wq0[q]; acc4 += h.y*wq1[q]; acc5 += h.y*wq2[q];
                }
            }
            __syncthreads();
        }

        if (w < 4){
            // GRU0 elementwise update for owned unit
            const int u = u0 + w;
            const float* gbase = g_gi0 + (size_t)step*768*BB;
            #pragma unroll
            for (int j = 0; j < 2; j++){
                int b = b0 + 2*l + j;
                float a0 = (j==0)?acc0:acc3;
                float a1 = (j==0)?acc1:acc4;
                float a2 = (j==0)?acc2:acc5;
                float gr = gbase[(size_t)u*BB + b];
                float gz = gbase[(size_t)(256+u)*BB + b];
                float gn = gbase[(size_t)(512+u)*BB + b];
                float r = sigmoidf_(gr + a0 + bA0);
                float z = sigmoidf_(gz + a1 + bA1);
                float hold = __ldcg(&g_h0[cur][u*BB + b]);
                float n = tanhf(gn + r*(a2 + bA2));
                float hnew = (1.f - z)*n + z*hold;
                g_h0[nxt][u*BB + b] = 0.1f*hold + 0.9f*hnew;
            }
        } else {
            // stash gh1 (pre-bias) for phase B
            const int ui = w - 4;
            int bl = l << 1;
            gh1s[(ui*3+0)*64 + bl]   = acc0;
            gh1s[(ui*3+1)*64 + bl]   = acc1;
            gh1s[(ui*3+2)*64 + bl]   = acc2;
            gh1s[(ui*3+0)*64 + bl+1] = acc3;
            gh1s[(ui*3+1)*64 + bl+1] = acc4;
            gh1s[(ui*3+2)*64 + bl+1] = acc5;
        }
        __threadfence();
        grid_barrier();

        // ---------------- Phase B: gi1 = h0_new@Wih1^T, GRU1 update --------
        float c0a=0.f, c1a=0.f, c2a=0.f;
        const float* vr0 = wB + (uiB*3+0)*256;
        const float* vr1 = wB + (uiB*3+1)*256;
        const float* vr2 = wB + (uiB*3+2)*256;
        for (int kt = 0; kt < 4; kt++){
            for (int i = t; i < 1024; i += 256){
                int k = i >> 4, b4 = i & 15;
                ((float4*)hs0)[i] = __ldcg((const float4*)&g_h0[nxt][(kt*64+k)*BB + b0 + b4*4]);
            }
            __syncthreads();
            const float* vp0 = vr0 + kt*64;
            const float* vp1 = vr1 + kt*64;
            const float* vp2 = vr2 + kt*64;
            #pragma unroll
            for (int k = 0; k < 64; k += 4){
                float wq0[4], wq1[4], wq2[4];
                *(float4*)wq0 = *(const float4*)&vp0[k];
                *(float4*)wq1 = *(const float4*)&vp1[k];
                *(float4*)wq2 = *(const float4*)&vp2[k];
                #pragma unroll
                for (int q = 0; q < 4; q++){
                    float h = hs0[(k+q)*64 + blB];
                    c0a += h*wq0[q]; c1a += h*wq1[q]; c2a += h*wq2[q];
                }
            }
            __syncthreads();
        }
        {
            int b = b0 + blB;
            float gr  = c0a + bI0 + gh1s[(uiB*3+0)*64 + blB] + bH0;
            float gz  = c1a + bI1 + gh1s[(uiB*3+1)*64 + blB] + bH1;
            float gnI = c2a + bI2;
            float ghn = gh1s[(uiB*3+2)*64 + blB] + bH2;
            float r = sigmoidf_(gr);
            float z = sigmoidf_(gz);
            float hold = __ldcg(&g_h1[uB*BB + b]);
            float n = tanhf(gnI + r*ghn);
            float hnew = (1.f - z)*n + z*hold;
            float hout = 0.1f*hold + 0.9f*hnew;
            g_h1[uB*BB + b] = hout;
            g_H[((size_t)step*256 + uB)*BB + b] = hout;
        }
        __threadfence();
        grid_barrier();
    }
}

// ---------------- kernel 4: MDN head GEMM + softmax/elu epilogue ------------
__global__ __launch_bounds__(256) void out_gemm(const float* __restrict__ enc,
    const float* __restrict__ Wpi, const float* __restrict__ bpi,
    const float* __restrict__ Wsg, const float* __restrict__ bsg,
    const float* __restrict__ Wmu, const float* __restrict__ bmu,
    float* __restrict__ out)
{
    __shared__ float As[32][68];
    __shared__ float Ws[32][96];
    __shared__ float Rs[64][96];
    const int s  = blockIdx.y;
    const int b0 = blockIdx.x * 64;
    const int t  = threadIdx.x;
    const int bg = t & 15, cg = t >> 4;
    float acc[6][4];
    #pragma unroll
    for (int i = 0; i < 6; i++)
        #pragma unroll
        for (int j = 0; j < 4; j++) acc[i][j] = 0.f;

    for (int kk = 0; kk < 512; kk += 32){
        for (int i = t; i < 2048; i += 256){
            int k = i >> 6, b = i & 63;
            int kg = kk + k;
            float v;
            if (kg < 256) v = g_H[((size_t)s*256 + kg)*BB + b0 + b];
            else          v = enc[(((size_t)(b0+b))*SS + s)*CC + (kg-256)];
            As[k][b] = v;
        }
        for (int i = t; i < 32*96; i += 256){
            int k = i/96, c = i - k*96;
            int kg = kk + k;
            float v = 0.f;
            if      (c < 10) v = Wpi[(size_t)c*512 + kg];
            else if (c < 50) v = Wsg[(size_t)(c-10)*512 + kg];
            else if (c < 90) v = Wmu[(size_t)(c-50)*512 + kg];
            Ws[k][c] = v;
        }
        __syncthreads();
        #pragma unroll 4
        for (int k = 0; k < 32; k++){
            float4 a = *(const float4*)&As[k][bg*4];
            #pragma unroll
            for (int ci = 0; ci < 6; ci++){
                float wv = Ws[k][cg*6 + ci];
                acc[ci][0] += wv*a.x; acc[ci][1] += wv*a.y;
                acc[ci][2] += wv*a.z; acc[ci][3] += wv*a.w;
            }
        }
        __syncthreads();
    }
    #pragma unroll
    for (int ci = 0; ci < 6; ci++){
        int c = cg*6 + ci;
        float bias = (c < 10) ? bpi[c] : (c < 50) ? bsg[c-10] : (c < 90) ? bmu[c-50] : 0.f;
        #pragma unroll
        for (int bi = 0; bi < 4; bi++) Rs[bg*4+bi][c] = acc[ci][bi] + bias;
    }
    __syncthreads();

    // epilogue: softmax(pi), elu+1(sigma), mu
    if (t < 64){
        int b = b0 + t;
        float lv[10]; float m = -1e30f;
        #pragma unroll
        for (int g = 0; g < 10; g++){ lv[g] = Rs[t][g]; m = fmaxf(m, lv[g]); }
        float sum = 0.f;
        #pragma unroll
        for (int g = 0; g < 10; g++){ lv[g] = expf(lv[g]-m); sum += lv[g]; }
        float inv = 1.f/sum;
        size_t base = (size_t)OUT_PI + ((size_t)b*SS + s)*10;
        #pragma unroll
        for (int g = 0; g < 10; g++) out[base + g] = lv[g]*inv;
    }
    for (int i = t; i < 64*40; i += 256){
        int row = i/40, j = i - row*40;
        int b = b0 + row;
        float x  = Rs[row][10+j];
        float xm = Rs[row][50+j];
        size_t base = ((size_t)b*SS + s)*40 + j;
        out[(size_t)OUT_SG + base] = (x > 0.f) ? (x + 1.f) : expf(x);
        out[(size_t)OUT_MU + base] = xm;
    }
}

// ---------------- kernel 5: tgt copy + duration mask ------------------------
__global__ void tail_kernel(const float* __restrict__ tgt,
                            const int* __restrict__ dur,
                            float* __restrict__ out){
    if (blockIdx.x < 1024){
        int idx = blockIdx.x*256 + threadIdx.x;   // exactly 262144 elements
        out[idx] = tgt[idx];
    } else {
        int b = blockIdx.x - 1024;
        __shared__ int cnt;
        if (threadIdx.x == 0) cnt = 0;
        __syncthreads();
        int local = 0;
        for (int s = threadIdx.x; s < SS; s += 256) local += (dur[b*SS + s] > 0) ? 1 : 0;
        #pragma unroll
        for (int o = 16; o; o >>= 1) local += __shfl_down_sync(0xffffffffu, local, o);
        if ((threadIdx.x & 31) == 0) atomicAdd(&cnt, local);
        __syncthreads();
        int c = cnt;
        for (int s = threadIdx.x; s < SS; s += 256)
            out[OUT_MASK + b*SS + s] = (s >= c) ? 1.f : 0.f;
    }
}

// ---------------- launch -----------------------------------------------------
#define REC_SMEM ((24*256 + 12*256 + 64*64*2 + 12*64) * (int)sizeof(float))

extern "C" void kernel_launch(void* const* d_in, const int* in_sizes, int n_in,
                              void* d_out, int out_size)
{
    const float* enc   = (const float*)d_in[0];
    const float* tgt   = (const float*)d_in[1];
    const int*   dur   = (const int*)  d_in[2];
    const float* W_pre = (const float*)d_in[3];
    const float* b_pre = (const float*)d_in[4];
    const float* Wih0  = (const float*)d_in[5];
    const float* Whh0  = (const float*)d_in[6];
    const float* bih0  = (const float*)d_in[7];
    const float* bhh0  = (const float*)d_in[8];
    const float* Wih1  = (const float*)d_in[9];
    const float* Whh1  = (const float*)d_in[10];
    const float* bih1  = (const float*)d_in[11];
    const float* bhh1  = (const float*)d_in[12];
    const float* Wpi   = (const float*)d_in[13];
    const float* bpi   = (const float*)d_in[14];
    const float* Wsg   = (const float*)d_in[15];
    const float* bsg   = (const float*)d_in[16];
    const float* Wmu   = (const float*)d_in[17];
    const float* bmu   = (const float*)d_in[18];
    float* out = (float*)d_out;

    prenet_kernel<<<(BB*SS*DOO + 255)/256, 256>>>(tgt, W_pre, b_pre);

    dim3 g2(2, 12, SS);
    gi0_gemm<<<g2, 256>>>(enc, Wih0, bih0);

    cudaFuncSetAttribute(rec_kernel, cudaFuncAttributeMaxDynamicSharedMemorySize, REC_SMEM);
    rec_kernel<<<NCTA, 256, REC_SMEM>>>(Whh0, bhh0, Wih1, bih1, Whh1, bhh1);

    dim3 g4(2, SS);
    out_gemm<<<g4, 256>>>(enc, Wpi, bpi, Wsg, bsg, Wmu, bmu, out);

    tail_kernel<<<1024 + BB, 256>>>(tgt, dur, out);
}

// round 2
// speedup vs baseline: 1.2062x; 1.2062x over previous
#include <cuda_runtime.h>
#include <math.h>

#define BB   128
#define SS   512
#define CC   256
#define DOO  4
#define GG   10
#define NCTA 128
#define TPB  512

#define OUT_PI   (BB*SS*DOO)                    /* 262144  */
#define OUT_SG   (OUT_PI + BB*SS*GG)            /* 917504  */
#define OUT_MU   (OUT_SG + BB*SS*GG*DOO)        /* 3538944 */
#define OUT_MASK (OUT_MU + BB*SS*GG*DOO)        /* 6160384 */

// ---------------- scratch (static device globals; no cudaMalloc) ------------
__device__ float g_pn[BB*SS*DOO];                 // prenet output [b][s][d]
__device__ float g_gi0[(size_t)SS*768*BB];        // x@Wih0^T + bih0, layout [s][col][b]
__device__ float g_h0[2][256*BB];                 // h0 double buffer, [u][b]
__device__ float g_h1[256*BB];                    // h1, [u][b]
__device__ float g_H[(size_t)SS*256*BB];          // h1 history, [s][u][b]
__device__ volatile unsigned long long g_arrive[NCTA*16]; // padded flags (128B stride)
__device__ volatile unsigned long long g_release;

__device__ __forceinline__ float sigmoidf_(float x){ return 1.f/(1.f + expf(-x)); }

__device__ __forceinline__ void ffma2(unsigned long long &acc,
                                      unsigned long long a, unsigned long long b){
    asm("fma.rn.f32x2 %0, %1, %2, %0;" : "+l"(acc) : "l"(a), "l"(b));
}
__device__ __forceinline__ float2 u2f2(unsigned long long v){
    float2 f; asm("mov.b64 {%0,%1}, %2;" : "=f"(f.x), "=f"(f.y) : "l"(v)); return f;
}

// flag-array grid barrier: arrive flags (padded) + CTA0 aggregation + release word
__device__ __forceinline__ void gbar(unsigned long long e){
    __syncthreads();
    if (threadIdx.x == 0){
        __threadfence();
        g_arrive[blockIdx.x*16] = e;
    }
    if (blockIdx.x == 0){
        if (threadIdx.x < NCTA){
            while (g_arrive[threadIdx.x*16] < e) { }
        }
        __syncthreads();
        if (threadIdx.x == 0) g_release = e;
    }
    if (threadIdx.x == 0){
        while (g_release < e) { }
        __threadfence();
    }
    __syncthreads();
}

// ---------------- kernel 1: prenet = prev @ W_pre^T + b_pre -----------------
__global__ void prenet_kernel(const float* __restrict__ tgt,
                              const float* __restrict__ W_pre,
                              const float* __restrict__ b_pre){
    int idx = blockIdx.x*256 + threadIdx.x;
    if (idx >= BB*SS*DOO) return;
    int d = idx & 3;
    int s = (idx >> 2) & (SS-1);
    int b = idx >> 11;
    float v = b_pre[d];
    if (s > 0){
        const float* pv = tgt + ((size_t)(b*SS + s - 1))*DOO;
        #pragma unroll
        for (int e = 0; e < 4; e++) v += pv[e]*W_pre[d*DOO + e];
    }
    g_pn[idx] = v;
}

// ---------------- kernel 2: gi0 = xs @ Wih0^T + bih0 ------------------------
__global__ __launch_bounds__(256) void gi0_gemm(const float* __restrict__ enc,
                                                const float* __restrict__ Wih0,
                                                const float* __restrict__ bih0){
    __shared__ float As[32][68];
    __shared__ float Ws[32][68];
    const int s  = blockIdx.z;
    const int c0 = blockIdx.y * 64;
    const int b0 = blockIdx.x * 64;
    const int t  = threadIdx.x;
    const int bg = t & 15, cg = t >> 4;
    float acc[4][4];
    #pragma unroll
    for (int i = 0; i < 4; i++)
        #pragma unroll
        for (int j = 0; j < 4; j++) acc[i][j] = 0.f;

    for (int kk = 0; kk < 260; kk += 32){
        for (int i = t; i < 2048; i += 256){
            int k = i >> 6, b = i & 63;
            int kg = kk + k;
            float v = 0.f;
            if (kg < 260){
                if (kg < 256) v = enc[(((size_t)(b0+b))*SS + s)*CC + kg];
                else          v = g_pn[(((size_t)(b0+b))*SS + s)*DOO + (kg-256)];
            }
            As[k][b] = v;
        }
        for (int i = t; i < 2048; i += 256){
            int k = i >> 6, c = i & 63;
            int kg = kk + k;
            Ws[k][c] = (kg < 260) ? Wih0[(size_t)(c0+c)*260 + kg] : 0.f;
        }
        __syncthreads();
        #pragma unroll
        for (int k = 0; k < 32; k++){
            float4 a = *(const float4*)&As[k][bg*4];
            float4 w = *(const float4*)&Ws[k][cg*4];
            acc[0][0] += w.x*a.x; acc[0][1] += w.x*a.y; acc[0][2] += w.x*a.z; acc[0][3] += w.x*a.w;
            acc[1][0] += w.y*a.x; acc[1][1] += w.y*a.y; acc[1][2] += w.y*a.z; acc[1][3] += w.y*a.w;
            acc[2][0] += w.z*a.x; acc[2][1] += w.z*a.y; acc[2][2] += w.z*a.z; acc[2][3] += w.z*a.w;
            acc[3][0] += w.w*a.x; acc[3][1] += w.w*a.y; acc[3][2] += w.w*a.z; acc[3][3] += w.w*a.w;
        }
        __syncthreads();
    }
    #pragma unroll
    for (int ci = 0; ci < 4; ci++){
        int c = c0 + cg*4 + ci;
        float bias = bih0[c];
        float4 o = make_float4(acc[ci][0]+bias, acc[ci][1]+bias, acc[ci][2]+bias, acc[ci][3]+bias);
        *(float4*)&g_gi0[((size_t)s*768 + c)*BB + b0 + bg*4] = o;
    }
}

// ---------------- kernel 3: persistent GRU recurrence -----------------------
// 128 CTAs = 64 unit-groups (4 units) x 2 batch-halves (64 batches), 512 thr
__global__ void __launch_bounds__(TPB, 1) rec_kernel(
    const float* __restrict__ Whh0, const float* __restrict__ bhh0,
    const float* __restrict__ Wih1, const float* __restrict__ bih1,
    const float* __restrict__ Whh1, const float* __restrict__ bhh1)
{
    extern __shared__ float sm[];
    float* wAd = sm;                 // 24*512  : dup Whh0/Whh1 rows
    float* wBd = wAd + 24*512;       // 12*512  : dup Wih1 rows
    float* hs0 = wBd + 12*512;       // 256*64
    float* hs1 = hs0 + 16384;        // 256*64
    float* pA  = hs1 + 16384;        // 2*24*64 : phase-A partials (2 K-halves)
    float* pB  = pA + 3072;          // 4*12*64 : phase-B partials (4 K-quarters)

    const int t = threadIdx.x;
    const int w = t >> 5, l = t & 31;
    const int ug = blockIdx.x >> 1, bh = blockIdx.x & 1;
    const int u0 = ug*4, b0 = bh*64;

    // ---- load weight slices (duplicated pairs for FFMA2), resident all steps
    for (int i = t; i < 24*256; i += TPB){
        int row = i >> 8, k = i & 255;
        int tr = row/3, g = row - tr*3;
        float v;
        if (tr < 4) v = Whh0[(size_t)(g*256 + u0 + tr)*256 + k];
        else        v = Whh1[(size_t)(g*256 + u0 + tr - 4)*256 + k];
        wAd[row*512 + 2*k]   = v;
        wAd[row*512 + 2*k+1] = v;
    }
    for (int i = t; i < 12*256; i += TPB){
        int row = i >> 8, k = i & 255;
        int ui2 = row/3, g = row - ui2*3;
        float v = Wih1[(size_t)(g*256 + u0 + ui2)*256 + k];
        wBd[row*512 + 2*k]   = v;
        wBd[row*512 + 2*k+1] = v;
    }

    // ---- per-thread update constants (threads 0..255 own 4u x 64b items)
    const int ui = (t & 255) >> 6;
    const int bl = t & 63;
    const int u  = u0 + ui;
    float b0r=0,b0z=0,b0n=0,b1ir=0,b1iz=0,b1in=0,b1hr=0,b1hz=0,b1hn=0;
    if (t < 256){
        b0r=bhh0[u]; b0z=bhh0[256+u]; b0n=bhh0[512+u];
        b1ir=bih1[u]; b1iz=bih1[256+u]; b1in=bih1[512+u];
        b1hr=bhh1[u]; b1hz=bhh1[256+u]; b1hn=bhh1[512+u];
        g_h0[0][u*BB + b0 + bl] = 0.f;
        g_h1[u*BB + b0 + bl]    = 0.f;
    }

    unsigned long long epoch = g_release;   // epoch continuation across replays
    epoch++; gbar(epoch);

    for (int step = 0; step < SS; step++){
        const int cur = step & 1, nxt = cur ^ 1;

        // ------- stage h0[cur], h1 fully (one shot, MLP-overlapped) --------
        for (int i = t; i < 8192; i += TPB){
            int j = i & 4095; int k = j >> 4, b4 = j & 15;
            if (i < 4096) ((float4*)hs0)[j] = __ldcg((const float4*)&g_h0[cur][k*BB + b0 + b4*4]);
            else          ((float4*)hs1)[j] = __ldcg((const float4*)&g_h1[k*BB + b0 + b4*4]);
        }
        // prefetch gi0 for the update (hidden under phase-A compute)
        float gir=0.f, giz=0.f, gin=0.f;
        if (t < 256){
            const float* gb = g_gi0 + (size_t)step*768*BB;
            gir = __ldcg(&gb[(size_t)u*BB       + b0 + bl]);
            giz = __ldcg(&gb[(size_t)(256+u)*BB + b0 + bl]);
            gin = __ldcg(&gb[(size_t)(512+u)*BB + b0 + bl]);
        }
        __syncthreads();

        // ------- Phase A: gh0 = h0@Whh0^T (rows 0-11), gh1 = h1@Whh1^T (12-23)
        // 16 warps = 8 row-triples x 2 K-halves, FFMA2 packed over 2 batches
        {
            const int kh = w >> 3, rt = w & 7;
            const float* hptr = ((rt < 4) ? hs0 : hs1) + kh*(128*64) + (l << 1);
            const float* wd = wAd + (3*rt)*512 + kh*256;
            unsigned long long a0=0ULL, a1=0ULL, a2=0ULL;
            #pragma unroll 8
            for (int k = 0; k < 128; k += 2){
                ulonglong2 w0 = *(const ulonglong2*)(wd + 2*k);
                ulonglong2 w1 = *(const ulonglong2*)(wd + 512 + 2*k);
                ulonglong2 w2 = *(const ulonglong2*)(wd + 1024 + 2*k);
                unsigned long long hA = *(const unsigned long long*)(hptr + k*64);
                unsigned long long hB = *(const unsigned long long*)(hptr + (k+1)*64);
                ffma2(a0, hA, w0.x); ffma2(a1, hA, w1.x); ffma2(a2, hA, w2.x);
                ffma2(a0, hB, w0.y); ffma2(a1, hB, w1.y); ffma2(a2, hB, w2.y);
            }
            float* pa = pA + (kh*24 + 3*rt)*64 + (l << 1);
            *(float2*)&pa[0]   = u2f2(a0);
            *(float2*)&pa[64]  = u2f2(a1);
            *(float2*)&pa[128] = u2f2(a2);
        }
        __syncthreads();

        // ------- GRU0 elementwise update (threads 0..255) -------------------
        if (t < 256){
            int r0 = 3*ui;
            float s0 = pA[r0*64+bl]     + pA[(24+r0)*64+bl];
            float s1 = pA[(r0+1)*64+bl] + pA[(24+r0+1)*64+bl];
            float s2 = pA[(r0+2)*64+bl] + pA[(24+r0+2)*64+bl];
            float r = sigmoidf_(gir + s0 + b0r);
            float z = sigmoidf_(giz + s1 + b0z);
            float n = tanhf(gin + r*(s2 + b0n));
            float hold = hs0[u*64 + bl];
            float hnew = (1.f - z)*n + z*hold;
            g_h0[nxt][u*BB + b0 + bl] = 0.1f*hold + 0.9f*hnew;
        }
        epoch++; gbar(epoch);

        // ------- Phase B: gi1 = h0_new @ Wih1^T ------------------------------
        for (int i = t; i < 4096; i += TPB){
            int k = i >> 4, b4 = i & 15;
            ((float4*)hs0)[i] = __ldcg((const float4*)&g_h0[nxt][k*BB + b0 + b4*4]);
        }
        __syncthreads();
        {
            const int kq = w >> 2, rt2 = w & 3;
            const float* hptr = hs0 + kq*(64*64) + (l << 1);
            const float* vd = wBd + (3*rt2)*512 + kq*128;
            unsigned long long c0=0ULL, c1=0ULL, c2=0ULL;
            #pragma unroll 8
            for (int k = 0; k < 64; k += 2){
                ulonglong2 w0 = *(const ulonglong2*)(vd + 2*k);
                ulonglong2 w1 = *(const ulonglong2*)(vd + 512 + 2*k);
                ulonglong2 w2 = *(const ulonglong2*)(vd + 1024 + 2*k);
                unsigned long long hA = *(const unsigned long long*)(hptr + k*64);
                unsigned long long hB = *(const unsigned long long*)(hptr + (k+1)*64);
                ffma2(c0, hA, w0.x); ffma2(c1, hA, w1.x); ffma2(c2, hA, w2.x);
                ffma2(c0, hB, w0.y); ffma2(c1, hB, w1.y); ffma2(c2, hB, w2.y);
            }
            float* pb = pB + (kq*12 + 3*rt2)*64 + (l << 1);
            *(float2*)&pb[0]   = u2f2(c0);
            *(float2*)&pb[64]  = u2f2(c1);
            *(float2*)&pb[128] = u2f2(c2);
        }
        __syncthreads();

        // ------- GRU1 elementwise update (threads 0..255) -------------------
        if (t < 256){
            int r0 = 3*ui;
            float i0 = pB[r0*64+bl]     + pB[(12+r0)*64+bl]   + pB[(24+r0)*64+bl]   + pB[(36+r0)*64+bl]   + b1ir;
            float i1 = pB[(r0+1)*64+bl] + pB[(12+r0+1)*64+bl] + pB[(24+r0+1)*64+bl] + pB[(36+r0+1)*64+bl] + b1iz;
            float i2 = pB[(r0+2)*64+bl] + pB[(12+r0+2)*64+bl] + pB[(24+r0+2)*64+bl] + pB[(36+r0+2)*64+bl] + b1in;
            float hg0 = pA[(12+r0)*64+bl]   + pA[(36+r0)*64+bl]   + b1hr;
            float hg1 = pA[(12+r0+1)*64+bl] + pA[(36+r0+1)*64+bl] + b1hz;
            float hg2 = pA[(12+r0+2)*64+bl] + pA[(36+r0+2)*64+bl] + b1hn;
            float r = sigmoidf_(i0 + hg0);
            float z = sigmoidf_(i1 + hg1);
            float n = tanhf(i2 + r*hg2);
            float hold = hs1[u*64 + bl];
            float hnew = (1.f - z)*n + z*hold;
            float hout = 0.1f*hold + 0.9f*hnew;
            g_h1[u*BB + b0 + bl] = hout;
            g_H[((size_t)step*256 + u)*BB + b0 + bl] = hout;
        }
        epoch++; gbar(epoch);
    }
}

// ---------------- kernel 4: MDN head GEMM + softmax/elu epilogue ------------
__global__ __launch_bounds__(256) void out_gemm(const float* __restrict__ enc,
    const float* __restrict__ Wpi, const float* __restrict__ bpi,
    const float* __restrict__ Wsg, const float* __restrict__ bsg,
    const float* __restrict__ Wmu, const float* __restrict__ bmu,
    float* __restrict__ out)
{
    __shared__ float As[32][68];
    __shared__ float Ws[32][96];
    __shared__ float Rs[64][96];
    const int s  = blockIdx.y;
    const int b0 = blockIdx.x * 64;
    const int t  = threadIdx.x;
    const int bg = t & 15, cg = t >> 4;
    float acc[6][4];
    #pragma unroll
    for (int i = 0; i < 6; i++)
        #pragma unroll
        for (int j = 0; j < 4; j++) acc[i][j] = 0.f;

    for (int kk = 0; kk < 512; kk += 32){
        for (int i = t; i < 2048; i += 256){
            int k = i >> 6, b = i & 63;
            int kg = kk + k;
            float v;
            if (kg < 256) v = g_H[((size_t)s*256 + kg)*BB + b0 + b];
            else          v = enc[(((size_t)(b0+b))*SS + s)*CC + (kg-256)];
            As[k][b] = v;
        }
        for (int i = t; i < 32*96; i += 256){
            int k = i/96, c = i - k*96;
            int kg = kk + k;
            float v = 0.f;
            if      (c < 10) v = Wpi[(size_t)c*512 + kg];
            else if (c < 50) v = Wsg[(size_t)(c-10)*512 + kg];
            else if (c < 90) v = Wmu[(size_t)(c-50)*512 + kg];
            Ws[k][c] = v;
        }
        __syncthreads();
        #pragma unroll 4
        for (int k = 0; k < 32; k++){
            float4 a = *(const float4*)&As[k][bg*4];
            #pragma unroll
            for (int ci = 0; ci < 6; ci++){
                float wv = Ws[k][cg*6 + ci];
                acc[ci][0] += wv*a.x; acc[ci][1] += wv*a.y;
                acc[ci][2] += wv*a.z; acc[ci][3] += wv*a.w;
            }
        }
        __syncthreads();
    }
    #pragma unroll
    for (int ci = 0; ci < 6; ci++){
        int c = cg*6 + ci;
        float bias = (c < 10) ? bpi[c] : (c < 50) ? bsg[c-10] : (c < 90) ? bmu[c-50] : 0.f;
        #pragma unroll
        for (int bi = 0; bi < 4; bi++) Rs[bg*4+bi][c] = acc[ci][bi] + bias;
    }
    __syncthreads();

    if (t < 64){
        int b = b0 + t;
        float lv[10]; float m = -1e30f;
        #pragma unroll
        for (int g = 0; g < 10; g++){ lv[g] = Rs[t][g]; m = fmaxf(m, lv[g]); }
        float sum = 0.f;
        #pragma unroll
        for (int g = 0; g < 10; g++){ lv[g] = expf(lv[g]-m); sum += lv[g]; }
        float inv = 1.f/sum;
        size_t base = (size_t)OUT_PI + ((size_t)b*SS + s)*10;
        #pragma unroll
        for (int g = 0; g < 10; g++) out[base + g] = lv[g]*inv;
    }
    for (int i = t; i < 64*40; i += 256){
        int row = i/40, j = i - row*40;
        int b = b0 + row;
        float x  = Rs[row][10+j];
        float xm = Rs[row][50+j];
        size_t base = ((size_t)b*SS + s)*40 + j;
        out[(size_t)OUT_SG + base] = (x > 0.f) ? (x + 1.f) : expf(x);
        out[(size_t)OUT_MU + base] = xm;
    }
}

// ---------------- kernel 5: tgt copy + duration mask ------------------------
__global__ void tail_kernel(const float* __restrict__ tgt,
                            const int* __restrict__ dur,
                            float* __restrict__ out){
    if (blockIdx.x < 1024){
        int idx = blockIdx.x*256 + threadIdx.x;
        out[idx] = tgt[idx];
    } else {
        int b = blockIdx.x - 1024;
        __shared__ int cnt;
        if (threadIdx.x == 0) cnt = 0;
        __syncthreads();
        int local = 0;
        for (int s = threadIdx.x; s < SS; s += 256) local += (dur[b*SS + s] > 0) ? 1 : 0;
        #pragma unroll
        for (int o = 16; o; o >>= 1) local += __shfl_down_sync(0xffffffffu, local, o);
        if ((threadIdx.x & 31) == 0) atomicAdd(&cnt, local);
        __syncthreads();
        int c = cnt;
        for (int s = threadIdx.x; s < SS; s += 256)
            out[OUT_MASK + b*SS + s] = (s >= c) ? 1.f : 0.f;
    }
}

// ---------------- launch -----------------------------------------------------
#define REC_SMEM ((24*512 + 12*512 + 16384*2 + 3072 + 3072) * (int)sizeof(float))

extern "C" void kernel_launch(void* const* d_in, const int* in_sizes, int n_in,
                              void* d_out, int out_size)
{
    const float* enc   = (const float*)d_in[0];
    const float* tgt   = (const float*)d_in[1];
    const int*   dur   = (const int*)  d_in[2];
    const float* W_pre = (const float*)d_in[3];
    const float* b_pre = (const float*)d_in[4];
    const float* Wih0  = (const float*)d_in[5];
    const float* Whh0  = (const float*)d_in[6];
    const float* bih0  = (const float*)d_in[7];
    const float* bhh0  = (const float*)d_in[8];
    const float* Wih1  = (const float*)d_in[9];
    const float* Whh1  = (const float*)d_in[10];
    const float* bih1  = (const float*)d_in[11];
    const float* bhh1  = (const float*)d_in[12];
    const float* Wpi   = (const float*)d_in[13];
    const float* bpi   = (const float*)d_in[14];
    const float* Wsg   = (const float*)d_in[15];
    const float* bsg   = (const float*)d_in[16];
    const float* Wmu   = (const float*)d_in[17];
    const float* bmu   = (const float*)d_in[18];
    float* out = (float*)d_out;

    prenet_kernel<<<(BB*SS*DOO + 255)/256, 256>>>(tgt, W_pre, b_pre);

    dim3 g2(2, 12, SS);
    gi0_gemm<<<g2, 256>>>(enc, Wih0, bih0);

    cudaFuncSetAttribute(rec_kernel, cudaFuncAttributeMaxDynamicSharedMemorySize, REC_SMEM);
    rec_kernel<<<NCTA, TPB, REC_SMEM>>>(Whh0, bhh0, Wih1, bih1, Whh1, bhh1);

    dim3 g4(2, SS);
    out_gemm<<<g4, 256>>>(enc, Wpi, bpi, Wsg, bsg, Wmu, bmu, out);

    tail_kernel<<<1024 + BB, 256>>>(tgt, dur, out);
}

// round 3
// speedup vs baseline: 1.4654x; 1.2150x over previous
#include <cuda_runtime.h>
#include <math.h>

#define BB   128
#define SS   512
#define CC   256
#define DOO  4
#define GG   10
#define NCTA 128
#define TPB  512

#define OUT_PI   (BB*SS*DOO)                    /* 262144  */
#define OUT_SG   (OUT_PI + BB*SS*GG)            /* 917504  */
#define OUT_MU   (OUT_SG + BB*SS*GG*DOO)        /* 3538944 */
#define OUT_MASK (OUT_MU + BB*SS*GG*DOO)        /* 6160384 */

// ---------------- scratch (static device globals; no cudaMalloc) ------------
__device__ float g_pn[BB*SS*DOO];                 // prenet output [b][s][d]
__device__ float g_gi0[(size_t)SS*768*BB];        // x@Wih0^T + bih0, layout [s][col][b]
__device__ float g_h0[2][256*BB];                 // h0 double buffer, [u][b]
__device__ float g_h1[2][256*BB];                 // h1 double buffer, [u][b]
__device__ float g_H[(size_t)SS*256*BB];          // h1 history, [s][u][b]
__device__ volatile unsigned int g_arr[NCTA*32];  // arrive flags, 128B stride

__device__ __forceinline__ float sigmoidf_(float x){ return 1.f/(1.f + expf(-x)); }

__device__ __forceinline__ void ffma2(unsigned long long &acc,
                                      unsigned long long a, unsigned long long b){
    asm("fma.rn.f32x2 %0, %1, %2, %0;" : "+l"(acc) : "l"(a), "l"(b));
}
__device__ __forceinline__ float2 u2f2(unsigned long long v){
    float2 f; asm("mov.b64 {%0,%1}, %2;" : "=f"(f.x), "=f"(f.y) : "l"(v)); return f;
}

// all-peers grid barrier: 1 L2 round trip. Flags reset to 0 by init_kernel.
__device__ __forceinline__ void gbar(unsigned int tgt){
    __syncthreads();
    __threadfence();
    if (threadIdx.x == 0) g_arr[blockIdx.x*32] = tgt;
    if (threadIdx.x < NCTA){
        while (g_arr[threadIdx.x*32] < tgt) { }
    }
    __threadfence();
    __syncthreads();
}

// ---------------- kernel 0: per-launch state reset ---------------------------
__global__ void init_kernel(){
    int i = blockIdx.x*256 + threadIdx.x;   // grid 128*256 = 32768
    if (i < NCTA*32) g_arr[i] = 0u;
    g_h0[0][i] = 0.f; g_h0[1][i] = 0.f;
    g_h1[0][i] = 0.f; g_h1[1][i] = 0.f;
}

// ---------------- kernel 1: prenet = prev @ W_pre^T + b_pre -----------------
__global__ void prenet_kernel(const float* __restrict__ tgt,
                              const float* __restrict__ W_pre,
                              const float* __restrict__ b_pre){
    int idx = blockIdx.x*256 + threadIdx.x;
    if (idx >= BB*SS*DOO) return;
    int d = idx & 3;
    int s = (idx >> 2) & (SS-1);
    int b = idx >> 11;
    float v = b_pre[d];
    if (s > 0){
        const float* pv = tgt + ((size_t)(b*SS + s - 1))*DOO;
        #pragma unroll
        for (int e = 0; e < 4; e++) v += pv[e]*W_pre[d*DOO + e];
    }
    g_pn[idx] = v;
}

// ---------------- kernel 2: gi0 = xs @ Wih0^T + bih0 ------------------------
__global__ __launch_bounds__(256) void gi0_gemm(const float* __restrict__ enc,
                                                const float* __restrict__ Wih0,
                                                const float* __restrict__ bih0){
    __shared__ float As[32][68];
    __shared__ float Ws[32][68];
    const int s  = blockIdx.z;
    const int c0 = blockIdx.y * 64;
    const int b0 = blockIdx.x * 64;
    const int t  = threadIdx.x;
    const int bg = t & 15, cg = t >> 4;
    float acc[4][4];
    #pragma unroll
    for (int i = 0; i < 4; i++)
        #pragma unroll
        for (int j = 0; j < 4; j++) acc[i][j] = 0.f;

    for (int kk = 0; kk < 260; kk += 32){
        for (int i = t; i < 2048; i += 256){
            int k = i >> 6, b = i & 63;
            int kg = kk + k;
            float v = 0.f;
            if (kg < 260){
                if (kg < 256) v = enc[(((size_t)(b0+b))*SS + s)*CC + kg];
                else          v = g_pn[(((size_t)(b0+b))*SS + s)*DOO + (kg-256)];
            }
            As[k][b] = v;
        }
        for (int i = t; i < 2048; i += 256){
            int k = i >> 6, c = i & 63;
            int kg = kk + k;
            Ws[k][c] = (kg < 260) ? Wih0[(size_t)(c0+c)*260 + kg] : 0.f;
        }
        __syncthreads();
        #pragma unroll
        for (int k = 0; k < 32; k++){
            float4 a = *(const float4*)&As[k][bg*4];
            float4 w = *(const float4*)&Ws[k][cg*4];
            acc[0][0] += w.x*a.x; acc[0][1] += w.x*a.y; acc[0][2] += w.x*a.z; acc[0][3] += w.x*a.w;
            acc[1][0] += w.y*a.x; acc[1][1] += w.y*a.y; acc[1][2] += w.y*a.z; acc[1][3] += w.y*a.w;
            acc[2][0] += w.z*a.x; acc[2][1] += w.z*a.y; acc[2][2] += w.z*a.z; acc[2][3] += w.z*a.w;
            acc[3][0] += w.w*a.x; acc[3][1] += w.w*a.y; acc[3][2] += w.w*a.z; acc[3][3] += w.w*a.w;
        }
        __syncthreads();
    }
    #pragma unroll
    for (int ci = 0; ci < 4; ci++){
        int c = c0 + cg*4 + ci;
        float bias = bih0[c];
        float4 o = make_float4(acc[ci][0]+bias, acc[ci][1]+bias, acc[ci][2]+bias, acc[ci][3]+bias);
        *(float4*)&g_gi0[((size_t)s*768 + c)*BB + b0 + bg*4] = o;
    }
}

// ---------------- kernel 3: persistent GRU recurrence, 1 barrier/phase ------
// Phase ph (0..512): h0_out[ph] = GRU0(x[ph], h0_out[ph-1])        (ph<512)
//                    h1_out[ph-1] = GRU1(h0_out[ph-1], h1_out[ph-2]) (ph>=1)
// 128 CTAs = 64 unit-groups (4 units) x 2 batch-halves (64 batches), 512 thr.
// 36 gate-rows per CTA: rows 0-11 gh0(Whh0), 12-23 gi1(Wih1), 24-35 gh1(Whh1).
__global__ void __launch_bounds__(TPB, 1) rec_kernel(
    const float* __restrict__ Whh0, const float* __restrict__ bhh0,
    const float* __restrict__ Wih1, const float* __restrict__ bih1,
    const float* __restrict__ Whh1, const float* __restrict__ bhh1)
{
    extern __shared__ float sm[];
    float* wAd = sm;                 // 36*512  : dup weight rows      (72 KB)
    float* hs0 = wAd + 36*512;       // 256*64  : h0_out[ph-1] staging (64 KB)
    float* hs1 = hs0 + 16384;        // 256*64  : h1_out[ph-2] staging (64 KB)
    float* pA  = hs1 + 16384;        // 2*24*64 : partials rows 0-23 (2 k-halves)
    float* pC  = pA + 3072;          // 12*64   : full sums rows 24-35

    const int t = threadIdx.x;
    const int w = t >> 5, l = t & 31;
    const int ug = blockIdx.x >> 1, bh = blockIdx.x & 1;
    const int u0 = ug*4, b0 = bh*64;

    // ---- load 36 weight rows (duplicated pairs for FFMA2), resident all run
    for (int i = t; i < 36*256; i += TPB){
        int row = i >> 8, k = i & 255;
        int g3 = row/12, rr = row - g3*12;
        int ui2 = rr/3, g = rr - ui2*3;
        const float* W = (g3 == 0) ? Whh0 : (g3 == 1) ? Wih1 : Whh1;
        float v = W[(size_t)(g*256 + u0 + ui2)*256 + k];
        wAd[row*512 + 2*k]   = v;
        wAd[row*512 + 2*k+1] = v;
    }

    // ---- per-thread update constants (threads 0..255: 4 units x 64 batches)
    const int ui = (t & 255) >> 6;
    const int bl = t & 63;
    const int u  = u0 + ui;
    float b0r=0,b0z=0,b0n=0,b1ir=0,b1iz=0,b1in=0,b1hr=0,b1hz=0,b1hn=0;
    if (t < 256){
        b0r=bhh0[u]; b0z=bhh0[256+u]; b0n=bhh0[512+u];
        b1ir=bih1[u]; b1iz=bih1[256+u]; b1in=bih1[512+u];
        b1hr=bhh1[u]; b1hz=bhh1[256+u]; b1hn=bhh1[512+u];
    }

    for (int ph = 0; ph < 513; ph++){
        // ------- stage h0_out[ph-1] and h1_out[ph-2] (one shot) -------------
        const float* src0 = g_h0[(ph+1) & 1];
        const float* src1 = g_h1[ph & 1];
        for (int i = t; i < 8192; i += TPB){
            int j = i & 4095; int k = j >> 4, b4 = j & 15;
            if (i < 4096) ((float4*)hs0)[j] = __ldcg((const float4*)&src0[k*BB + b0 + b4*4]);
            else          ((float4*)hs1)[j] = __ldcg((const float4*)&src1[k*BB + b0 + b4*4]);
        }
        // prefetch gi0 for GRU0 update
        float gir=0.f, giz=0.f, gin=0.f;
        if (t < 256 && ph < 512){
            const float* gb = g_gi0 + (size_t)ph*768*BB;
            gir = __ldcg(&gb[(size_t)u*BB       + b0 + bl]);
            giz = __ldcg(&gb[(size_t)(256+u)*BB + b0 + bl]);
            gin = __ldcg(&gb[(size_t)(512+u)*BB + b0 + bl]);
        }
        __syncthreads();

        // ------- fused 3-GEMM: 36 rows x 64 batch x 256 k -------------------
        if (w < 12){
            // rows 0..23 (hs0 source), 12 warps = 2 k-halves x 6 row-groups(4)
            const int kh = w / 6, rg = w - 6*(w/6);
            const float* hp = hs0 + kh*(128*64) + (l << 1);
            const float* wd = wAd + (rg*4)*512 + kh*256;
            unsigned long long a0=0ULL,a1=0ULL,a2=0ULL,a3=0ULL;
            #pragma unroll 8
            for (int k = 0; k < 128; k += 2){
                ulonglong2 w0 = *(const ulonglong2*)(wd + 2*k);
                ulonglong2 w1 = *(const ulonglong2*)(wd + 512  + 2*k);
                ulonglong2 w2 = *(const ulonglong2*)(wd + 1024 + 2*k);
                ulonglong2 w3 = *(const ulonglong2*)(wd + 1536 + 2*k);
                unsigned long long hA = *(const unsigned long long*)(hp + k*64);
                unsigned long long hB = *(const unsigned long long*)(hp + (k+1)*64);
                ffma2(a0, hA, w0.x); ffma2(a1, hA, w1.x);
                ffma2(a2, hA, w2.x); ffma2(a3, hA, w3.x);
                ffma2(a0, hB, w0.y); ffma2(a1, hB, w1.y);
                ffma2(a2, hB, w2.y); ffma2(a3, hB, w3.y);
            }
            float* pa = pA + (kh*24 + rg*4)*64 + (l << 1);
            *(float2*)&pa[0]   = u2f2(a0);
            *(float2*)&pa[64]  = u2f2(a1);
            *(float2*)&pa[128] = u2f2(a2);
            *(float2*)&pa[192] = u2f2(a3);
        } else {
            // rows 24..35 (hs1 source), 4 warps x 3 rows, full k=256
            const int rg = w - 12;
            const float* hp = hs1 + (l << 1);
            const float* wd = wAd + (24 + rg*3)*512;
            unsigned long long c0=0ULL,c1=0ULL,c2=0ULL;
            #pragma unroll 8
            for (int k = 0; k < 256; k += 2){
                ulonglong2 w0 = *(const ulonglong2*)(wd + 2*k);
                ulonglong2 w1 = *(const ulonglong2*)(wd + 512  + 2*k);
                ulonglong2 w2 = *(const ulonglong2*)(wd + 1024 + 2*k);
                unsigned long long hA = *(const unsigned long long*)(hp + k*64);
                unsigned long long hB = *(const unsigned long long*)(hp + (k+1)*64);
                ffma2(c0, hA, w0.x); ffma2(c1, hA, w1.x); ffma2(c2, hA, w2.x);
                ffma2(c0, hB, w0.y); ffma2(c1, hB, w1.y); ffma2(c2, hB, w2.y);
            }
            float* pc = pC + (rg*3)*64 + (l << 1);
            *(float2*)&pc[0]   = u2f2(c0);
            *(float2*)&pc[64]  = u2f2(c1);
            *(float2*)&pc[128] = u2f2(c2);
        }
        __syncthreads();

        // ------- elementwise updates (threads 0..255) ------------------------
        if (t < 256){
            int r0 = ui*3;
            if (ph < 512){
                // GRU0: h0_out[ph]
                float s0 = pA[r0*64+bl]     + pA[(24+r0)*64+bl];
                float s1 = pA[(r0+1)*64+bl] + pA[(24+r0+1)*64+bl];
                float s2 = pA[(r0+2)*64+bl] + pA[(24+r0+2)*64+bl];
                float r = sigmoidf_(gir + s0 + b0r);
                float z = sigmoidf_(giz + s1 + b0z);
                float n = tanhf(gin + r*(s2 + b0n));
                float hold = hs0[u*64 + bl];
                float hnew = (1.f - z)*n + z*hold;
                g_h0[ph & 1][u*BB + b0 + bl] = 0.1f*hold + 0.9f*hnew;
            }
            if (ph >= 1){
                // GRU1: h1_out[ph-1]
                int q0 = 12 + r0;
                float i0 = pA[q0*64+bl]     + pA[(24+q0)*64+bl]     + b1ir;
                float i1 = pA[(q0+1)*64+bl] + pA[(24+q0+1)*64+bl]   + b1iz;
                float i2 = pA[(q0+2)*64+bl] + pA[(24+q0+2)*64+bl]   + b1in;
                float hg0 = pC[r0*64+bl]     + b1hr;
                float hg1 = pC[(r0+1)*64+bl] + b1hz;
                float hg2 = pC[(r0+2)*64+bl] + b1hn;
                float r = sigmoidf_(i0 + hg0);
                float z = sigmoidf_(i1 + hg1);
                float n = tanhf(i2 + r*hg2);
                float hold = hs1[u*64 + bl];
                float hnew = (1.f - z)*n + z*hold;
                float hout = 0.1f*hold + 0.9f*hnew;
                g_h1[(ph+1) & 1][u*BB + b0 + bl] = hout;
                g_H[((size_t)(ph-1)*256 + u)*BB + b0 + bl] = hout;
            }
        }
        gbar((unsigned int)(ph+1));
    }
}

// ---------------- kernel 4: MDN head GEMM + softmax/elu epilogue ------------
__global__ __launch_bounds__(256) void out_gemm(const float* __restrict__ enc,
    const float* __restrict__ Wpi, const float* __restrict__ bpi,
    const float* __restrict__ Wsg, const float* __restrict__ bsg,
    const float* __restrict__ Wmu, const float* __restrict__ bmu,
    float* __restrict__ out)
{
    __shared__ float As[32][68];
    __shared__ float Ws[32][96];
    __shared__ float Rs[64][96];
    const int s  = blockIdx.y;
    const int b0 = blockIdx.x * 64;
    const int t  = threadIdx.x;
    const int bg = t & 15, cg = t >> 4;
    float acc[6][4];
    #pragma unroll
    for (int i = 0; i < 6; i++)
        #pragma unroll
        for (int j = 0; j < 4; j++) acc[i][j] = 0.f;

    for (int kk = 0; kk < 512; kk += 32){
        for (int i = t; i < 2048; i += 256){
            int k = i >> 6, b = i & 63;
            int kg = kk + k;
            float v;
            if (kg < 256) v = g_H[((size_t)s*256 + kg)*BB + b0 + b];
            else          v = enc[(((size_t)(b0+b))*SS + s)*CC + (kg-256)];
            As[k][b] = v;
        }
        for (int i = t; i < 32*96; i += 256){
            int k = i/96, c = i - k*96;
            int kg = kk + k;
            float v = 0.f;
            if      (c < 10) v = Wpi[(size_t)c*512 + kg];
            else if (c < 50) v = Wsg[(size_t)(c-10)*512 + kg];
            else if (c < 90) v = Wmu[(size_t)(c-50)*512 + kg];
            Ws[k][c] = v;
        }
        __syncthreads();
        #pragma unroll 4
        for (int k = 0; k < 32; k++){
            float4 a = *(const float4*)&As[k][bg*4];
            #pragma unroll
            for (int ci = 0; ci < 6; ci++){
                float wv = Ws[k][cg*6 + ci];
                acc[ci][0] += wv*a.x; acc[ci][1] += wv*a.y;
                acc[ci][2] += wv*a.z; acc[ci][3] += wv*a.w;
            }
        }
        __syncthreads();
    }
    #pragma unroll
    for (int ci = 0; ci < 6; ci++){
        int c = cg*6 + ci;
        float bias = (c < 10) ? bpi[c] : (c < 50) ? bsg[c-10] : (c < 90) ? bmu[c-50] : 0.f;
        #pragma unroll
        for (int bi = 0; bi < 4; bi++) Rs[bg*4+bi][c] = acc[ci][bi] + bias;
    }
    __syncthreads();

    if (t < 64){
        int b = b0 + t;
        float lv[10]; float m = -1e30f;
        #pragma unroll
        for (int g = 0; g < 10; g++){ lv[g] = Rs[t][g]; m = fmaxf(m, lv[g]); }
        float sum = 0.f;
        #pragma unroll
        for (int g = 0; g < 10; g++){ lv[g] = expf(lv[g]-m); sum += lv[g]; }
        float inv = 1.f/sum;
        size_t base = (size_t)OUT_PI + ((size_t)b*SS + s)*10;
        #pragma unroll
        for (int g = 0; g < 10; g++) out[base + g] = lv[g]*inv;
    }
    for (int i = t; i < 64*40; i += 256){
        int row = i/40, j = i - row*40;
        int b = b0 + row;
        float x  = Rs[row][10+j];
        float xm = Rs[row][50+j];
        size_t base = ((size_t)b*SS + s)*40 + j;
        out[(size_t)OUT_SG + base] = (x > 0.f) ? (x + 1.f) : expf(x);
        out[(size_t)OUT_MU + base] = xm;
    }
}

// ---------------- kernel 5: tgt copy + duration mask ------------------------
__global__ void tail_kernel(const float* __restrict__ tgt,
                            const int* __restrict__ dur,
                            float* __restrict__ out){
    if (blockIdx.x < 1024){
        int idx = blockIdx.x*256 + threadIdx.x;
        out[idx] = tgt[idx];
    } else {
        int b = blockIdx.x - 1024;
        __shared__ int cnt;
        if (threadIdx.x == 0) cnt = 0;
        __syncthreads();
        int local = 0;
        for (int s = threadIdx.x; s < SS; s += 256) local += (dur[b*SS + s] > 0) ? 1 : 0;
        #pragma unroll
        for (int o = 16; o; o >>= 1) local += __shfl_down_sync(0xffffffffu, local, o);
        if ((threadIdx.x & 31) == 0) atomicAdd(&cnt, local);
        __syncthreads();
        int c = cnt;
        for (int s = threadIdx.x; s < SS; s += 256)
            out[OUT_MASK + b*SS + s] = (s >= c) ? 1.f : 0.f;
    }
}

// ---------------- launch -----------------------------------------------------
#define REC_SMEM ((36*512 + 16384*2 + 2*24*64 + 12*64) * (int)sizeof(float))

extern "C" void kernel_launch(void* const* d_in, const int* in_sizes, int n_in,
                              void* d_out, int out_size)
{
    const float* enc   = (const float*)d_in[0];
    const float* tgt   = (const float*)d_in[1];
    const int*   dur   = (const int*)  d_in[2];
    const float* W_pre = (const float*)d_in[3];
    const float* b_pre = (const float*)d_in[4];
    const float* Wih0  = (const float*)d_in[5];
    const float* Whh0  = (const float*)d_in[6];
    const float* bih0  = (const float*)d_in[7];
    const float* bhh0  = (const float*)d_in[8];
    const float* Wih1  = (const float*)d_in[9];
    const float* Whh1  = (const float*)d_in[10];
    const float* bih1  = (const float*)d_in[11];
    const float* bhh1  = (const float*)d_in[12];
    const float* Wpi   = (const float*)d_in[13];
    const float* bpi   = (const float*)d_in[14];
    const float* Wsg   = (const float*)d_in[15];
    const float* bsg   = (const float*)d_in[16];
    const float* Wmu   = (const float*)d_in[17];
    const float* bmu   = (const float*)d_in[18];
    float* out = (float*)d_out;

    init_kernel<<<128, 256>>>();

    prenet_kernel<<<(BB*SS*DOO + 255)/256, 256>>>(tgt, W_pre, b_pre);

    dim3 g2(2, 12, SS);
    gi0_gemm<<<g2, 256>>>(enc, Wih0, bih0);

    cudaFuncSetAttribute(rec_kernel, cudaFuncAttributeMaxDynamicSharedMemorySize, REC_SMEM);
    rec_kernel<<<NCTA, TPB, REC_SMEM>>>(Whh0, bhh0, Wih1, bih1, Whh1, bhh1);

    dim3 g4(2, SS);
    out_gemm<<<g4, 256>>>(enc, Wpi, bpi, Wsg, bsg, Wmu, bmu, out);

    tail_kernel<<<1024 + BB, 256>>>(tgt, dur, out);
}